// round 1
// baseline (speedup 1.0000x reference)
#include <cuda_runtime.h>
#include <cstdint>
#include <cstddef>

// Problem constants
#define NTOK 16384
#define DIN  512
#define DOUT 512
#define NEXP 16

// GEMM tiling
#define BM 128
#define BN 128
#define BK 16
#define PADA 20   // smem row stride (floats) for A tile [BM][BK]
#define PADB 20   // smem row stride (floats) for B tile [BN][BK] (stored n-major)

// ---------------- device scratch (static: no runtime allocation) --------------
__device__ int   g_counts[NEXP];
__device__ int   g_tok [NEXP * NTOK];   // gathered token id per expert slot
__device__ int   g_dest[NEXP * NTOK];   // destination slot = 2*token + k
__device__ float g_wt  [NEXP * NTOK];   // routing weight per slot
__device__ float g_scratch[(size_t)NTOK * 2 * DOUT]; // 64 MB: per-(token,k) weighted expert output

// ---------------- kernel 0: zero the per-expert counters ---------------------
__global__ void zero_counts_kernel() {
    if (threadIdx.x < NEXP) g_counts[threadIdx.x] = 0;
}

// ---------------- kernel 1: router (logits + top2 + softmax + dispatch) ------
// One warp per token. Lane l accumulates partial dot over d = l, l+32, ...
__global__ void router_kernel(const float* __restrict__ x,
                              const float* __restrict__ gw,
                              const float* __restrict__ gb) {
    int gwarp = (blockIdx.x * blockDim.x + threadIdx.x) >> 5;
    int lane  = threadIdx.x & 31;
    if (gwarp >= NTOK) return;

    const float* xr = x + (size_t)gwarp * DIN;
    float acc[NEXP];
#pragma unroll
    for (int e = 0; e < NEXP; e++) acc[e] = 0.f;

#pragma unroll
    for (int s = 0; s < DIN / 32; s++) {
        int d = s * 32 + lane;
        float xv = __ldg(xr + d);
        const float4* g4 = reinterpret_cast<const float4*>(gw + (size_t)d * NEXP);
        float4 a = __ldg(g4 + 0);
        float4 b = __ldg(g4 + 1);
        float4 c = __ldg(g4 + 2);
        float4 dd = __ldg(g4 + 3);
        acc[0]  += xv * a.x;  acc[1]  += xv * a.y;  acc[2]  += xv * a.z;  acc[3]  += xv * a.w;
        acc[4]  += xv * b.x;  acc[5]  += xv * b.y;  acc[6]  += xv * b.z;  acc[7]  += xv * b.w;
        acc[8]  += xv * c.x;  acc[9]  += xv * c.y;  acc[10] += xv * c.z;  acc[11] += xv * c.w;
        acc[12] += xv * dd.x; acc[13] += xv * dd.y; acc[14] += xv * dd.z; acc[15] += xv * dd.w;
    }

#pragma unroll
    for (int e = 0; e < NEXP; e++) {
#pragma unroll
        for (int off = 16; off > 0; off >>= 1)
            acc[e] += __shfl_xor_sync(0xffffffffu, acc[e], off);
    }

    if (lane == 0) {
        float v[NEXP];
#pragma unroll
        for (int e = 0; e < NEXP; e++) v[e] = acc[e] + gb[e];

        // top-1
        float v0 = v[0]; int e0 = 0;
#pragma unroll
        for (int e = 1; e < NEXP; e++) { if (v[e] > v0) { v0 = v[e]; e0 = e; } }
        // top-2
        float v1 = -3.402823466e38f; int e1 = -1;
#pragma unroll
        for (int e = 0; e < NEXP; e++) { if (e != e0 && v[e] > v1) { v1 = v[e]; e1 = e; } }

        // softmax over the two selected logits (v0 >= v1)
        float ex  = expf(v1 - v0);
        float inv = 1.f / (1.f + ex);
        float w0  = inv;
        float w1  = ex * inv;

        int p0 = atomicAdd(&g_counts[e0], 1);
        g_tok [e0 * NTOK + p0] = gwarp;
        g_dest[e0 * NTOK + p0] = 2 * gwarp;
        g_wt  [e0 * NTOK + p0] = w0;

        int p1 = atomicAdd(&g_counts[e1], 1);
        g_tok [e1 * NTOK + p1] = gwarp;
        g_dest[e1 * NTOK + p1] = 2 * gwarp + 1;
        g_wt  [e1 * NTOK + p1] = w1;
    }
}

// ---------------- tf32 helpers ------------------------------------------------
__device__ __forceinline__ uint32_t f2tf(float f) {
    uint32_t u;
    asm("cvt.rna.tf32.f32 %0, %1;" : "=r"(u) : "f"(f));
    return u;
}

// ---------------- kernel 2: grouped GEMM (tf32 mma.sync) ----------------------
// grid: (128 m-tiles, 4 n-tiles, 16 experts), 256 threads (8 warps, 2x4 warp grid).
// Each block: [BM tokens x BN outs], K = 512 in 32 BK=16 double-buffered stages.
__global__ __launch_bounds__(256)
void moe_gemm_kernel(const float* __restrict__ x,
                     const float* __restrict__ ew,
                     const float* __restrict__ eb) {
    int e = blockIdx.z;
    int cnt = g_counts[e];
    int mbase = blockIdx.x * BM;
    if (mbase >= cnt) return;            // idle tile: quick exit
    int nbase = blockIdx.y * BN;

    __shared__ uint32_t As[2][BM * PADA];
    __shared__ uint32_t Bs[2][BN * PADB];

    const int tid  = threadIdx.x;
    const int lane = tid & 31;
    const int wid  = tid >> 5;
    const int wm   = (wid & 1) * 64;     // warp m offset in tile
    const int wn   = (wid >> 1) * 32;    // warp n offset in tile

    const int*   tokp = g_tok + e * NTOK;
    const float* Bg   = ew + (size_t)e * DIN * DOUT;

    // A loader mapping: 512 float4 items, thread covers items {tid, tid+256}
    const int ar0 = tid >> 2;            // rows 0..63
    const int ac  = (tid & 3) * 4;       // col offset 0,4,8,12
    const int ar1 = ar0 + 64;            // rows 64..127
    int t0 = (mbase + ar0 < cnt) ? tokp[mbase + ar0] : -1;
    int t1 = (mbase + ar1 < cnt) ? tokp[mbase + ar1] : -1;
    const float* xa0 = (t0 >= 0) ? (x + (size_t)t0 * DIN + ac) : nullptr;
    const float* xa1 = (t1 >= 0) ? (x + (size_t)t1 * DIN + ac) : nullptr;

    // B loader mapping: k = tid&15, n4 = tid>>4 ; items {tid, tid+256} -> n, n+64
    const int bk = tid & 15;
    const int bn = (tid >> 4) * 4;       // 0..60 step 4
    const float* bg0 = Bg + (size_t)bk * DOUT + nbase + bn;        // second item: +64 cols

    float acc[4][4][4];
#pragma unroll
    for (int i = 0; i < 4; i++)
#pragma unroll
        for (int j = 0; j < 4; j++)
#pragma unroll
            for (int r = 0; r < 4; r++) acc[i][j][r] = 0.f;

    float4 pa0, pa1, pb0, pb1;

    // ---- fetch stage kt into registers
    auto fetch = [&](int kt) {
        int koff = kt * BK;
        pa0 = make_float4(0.f, 0.f, 0.f, 0.f);
        pa1 = pa0;
        if (xa0) pa0 = *reinterpret_cast<const float4*>(xa0 + koff);
        if (xa1) pa1 = *reinterpret_cast<const float4*>(xa1 + koff);
        pb0 = *reinterpret_cast<const float4*>(bg0 + (size_t)koff * DOUT);
        pb1 = *reinterpret_cast<const float4*>(bg0 + (size_t)koff * DOUT + 64);
    };

    // ---- convert + store staged registers into smem buffer
    auto stage = [&](int buf) {
        uint32_t* sa = As[buf];
        uint4 u0 = make_uint4(f2tf(pa0.x), f2tf(pa0.y), f2tf(pa0.z), f2tf(pa0.w));
        uint4 u1 = make_uint4(f2tf(pa1.x), f2tf(pa1.y), f2tf(pa1.z), f2tf(pa1.w));
        *reinterpret_cast<uint4*>(sa + ar0 * PADA + ac) = u0;
        *reinterpret_cast<uint4*>(sa + ar1 * PADA + ac) = u1;
        uint32_t* sb = Bs[buf];
        sb[(bn + 0) * PADB + bk] = f2tf(pb0.x);
        sb[(bn + 1) * PADB + bk] = f2tf(pb0.y);
        sb[(bn + 2) * PADB + bk] = f2tf(pb0.z);
        sb[(bn + 3) * PADB + bk] = f2tf(pb0.w);
        sb[(bn + 64) * PADB + bk] = f2tf(pb1.x);
        sb[(bn + 65) * PADB + bk] = f2tf(pb1.y);
        sb[(bn + 66) * PADB + bk] = f2tf(pb1.z);
        sb[(bn + 67) * PADB + bk] = f2tf(pb1.w);
    };

    // ---- compute one BK=16 stage out of smem buffer
    auto compute = [&](int buf) {
        const uint32_t* sa = As[buf];
        const uint32_t* sb = Bs[buf];
#pragma unroll
        for (int ks = 0; ks < 2; ks++) {
            int kk = ks * 8 + (lane & 3);
            uint32_t a[4][4];
#pragma unroll
            for (int mf = 0; mf < 4; mf++) {
                int rb = wm + mf * 16 + (lane >> 2);
                a[mf][0] = sa[rb * PADA + kk];
                a[mf][1] = sa[(rb + 8) * PADA + kk];
                a[mf][2] = sa[rb * PADA + kk + 4];
                a[mf][3] = sa[(rb + 8) * PADA + kk + 4];
            }
            uint32_t b[4][2];
#pragma unroll
            for (int nf = 0; nf < 4; nf++) {
                int nb = wn + nf * 8 + (lane >> 2);
                b[nf][0] = sb[nb * PADB + kk];
                b[nf][1] = sb[nb * PADB + kk + 4];
            }
#pragma unroll
            for (int mf = 0; mf < 4; mf++)
#pragma unroll
                for (int nf = 0; nf < 4; nf++) {
                    asm volatile(
                        "mma.sync.aligned.m16n8k8.row.col.f32.tf32.tf32.f32 "
                        "{%0,%1,%2,%3}, {%4,%5,%6,%7}, {%8,%9}, {%0,%1,%2,%3};"
                        : "+f"(acc[mf][nf][0]), "+f"(acc[mf][nf][1]),
                          "+f"(acc[mf][nf][2]), "+f"(acc[mf][nf][3])
                        : "r"(a[mf][0]), "r"(a[mf][1]), "r"(a[mf][2]), "r"(a[mf][3]),
                          "r"(b[nf][0]), "r"(b[nf][1]));
                }
        }
    };

    // ---- mainloop: double buffered
    fetch(0);
    stage(0);
    __syncthreads();
#pragma unroll 1
    for (int kt = 0; kt < DIN / BK; kt++) {
        int buf = kt & 1;
        if (kt < DIN / BK - 1) fetch(kt + 1);
        compute(buf);
        if (kt < DIN / BK - 1) stage(buf ^ 1);
        __syncthreads();
    }

    // ---- epilogue: scale by routing weight, add bias, scatter to unique slot
    const float* ebp = eb + e * DOUT + nbase;
#pragma unroll
    for (int mf = 0; mf < 4; mf++) {
        int rl0 = wm + mf * 16 + (lane >> 2);
#pragma unroll
        for (int h = 0; h < 2; h++) {
            int r = mbase + rl0 + h * 8;
            if (r < cnt) {
                int dst  = g_dest[e * NTOK + r];
                float w  = g_wt [e * NTOK + r];
                float* outp = g_scratch + (size_t)dst * DOUT + nbase;
#pragma unroll
                for (int nf = 0; nf < 4; nf++) {
                    int n = wn + nf * 8 + (lane & 3) * 2;
                    float b0 = ebp[n], b1 = ebp[n + 1];
                    float2 v;
                    v.x = w * (acc[mf][nf][h * 2 + 0] + b0);
                    v.y = w * (acc[mf][nf][h * 2 + 1] + b1);
                    *reinterpret_cast<float2*>(outp + n) = v;
                }
            }
        }
    }
}

// ---------------- kernel 3: combine the two expert contributions --------------
__global__ void combine_kernel(float* __restrict__ out) {
    int idx = blockIdx.x * blockDim.x + threadIdx.x;   // float4 index, 0 .. NTOK*128
    int t = idx >> 7;
    int c = idx & 127;
    const float4* s = reinterpret_cast<const float4*>(g_scratch);
    float4 a = s[(size_t)t * 256 + c];
    float4 b = s[(size_t)t * 256 + 128 + c];
    float4 r;
    r.x = a.x + b.x; r.y = a.y + b.y; r.z = a.z + b.z; r.w = a.w + b.w;
    reinterpret_cast<float4*>(out)[idx] = r;
}

// ---------------- launch ------------------------------------------------------
extern "C" void kernel_launch(void* const* d_in, const int* in_sizes, int n_in,
                              void* d_out, int out_size) {
    (void)in_sizes; (void)n_in; (void)out_size;
    const float* x  = (const float*)d_in[0];
    const float* gw = (const float*)d_in[1];
    const float* gb = (const float*)d_in[2];
    const float* ew = (const float*)d_in[3];
    const float* eb = (const float*)d_in[4];
    float* out = (float*)d_out;

    zero_counts_kernel<<<1, 32>>>();
    router_kernel<<<NTOK / 8, 256>>>(x, gw, gb);
    dim3 ggrid(NTOK / BM, DOUT / BN, NEXP);
    moe_gemm_kernel<<<ggrid, 256>>>(x, ew, eb);
    combine_kernel<<<(NTOK * DOUT / 4) / 256, 256>>>(out);
}

// round 7
// speedup vs baseline: 1.8931x; 1.8931x over previous
#include <cuda_runtime.h>
#include <cuda_fp16.h>
#include <cstdint>
#include <cstddef>

// Problem constants
#define NTOK 16384
#define DIN  512
#define DOUT 512
#define NEXP 16

// GEMM tiling (fp16 mma.sync m16n8k16)
#define BM 128
#define BN 128
#define BK 32
#define KSTAGES (DIN / BK)     // 16
#define MAXTILES 272           // sum ceil(cnt_e/128) <= 32768/128 + 16
#define ASTAGE (BM * BK * 2)   // 8192 B
#define BSTAGE (BN * BK * 2)   // 8192 B

// ---------------- device scratch ----------------------------------------------
__device__ int   g_counts[NEXP];
__device__ int   g_tok [NEXP * NTOK];
__device__ int   g_dest[NEXP * NTOK];
__device__ float g_wt  [NEXP * NTOK];
__device__ float g_scratch[(size_t)NTOK * 2 * DOUT];         // 64 MB
__device__ __half g_xh[(size_t)NTOK * DIN];                  // x fp16
__device__ __half g_wth[(size_t)NEXP * DOUT * DIN];          // W^T fp16 [E][DOUT][DIN]

// ---------------- PTX helpers --------------------------------------------------
__device__ __forceinline__ uint32_t smem_u32(const void* p) {
    uint32_t a;
    asm("{ .reg .u64 t; cvta.to.shared.u64 t, %1; cvt.u32.u64 %0, t; }" : "=r"(a) : "l"(p));
    return a;
}
__device__ __forceinline__ void cp16(uint32_t dst, const void* src) {
    asm volatile("cp.async.cg.shared.global [%0], [%1], 16;" :: "r"(dst), "l"(src) : "memory");
}
__device__ __forceinline__ void ldsm_x4(uint32_t* r, uint32_t addr) {
    asm volatile("ldmatrix.sync.aligned.m8n8.x4.shared.b16 {%0,%1,%2,%3}, [%4];"
                 : "=r"(r[0]), "=r"(r[1]), "=r"(r[2]), "=r"(r[3]) : "r"(addr));
}
__device__ __forceinline__ void mma16816(float* d, const uint32_t* a, const uint32_t* b) {
    asm volatile("mma.sync.aligned.m16n8k16.row.col.f32.f16.f16.f32 "
                 "{%0,%1,%2,%3}, {%4,%5,%6,%7}, {%8,%9}, {%0,%1,%2,%3};"
                 : "+f"(d[0]), "+f"(d[1]), "+f"(d[2]), "+f"(d[3])
                 : "r"(a[0]), "r"(a[1]), "r"(a[2]), "r"(a[3]), "r"(b[0]), "r"(b[1]));
}

// ---------------- kernel 0: zero counters -------------------------------------
__global__ void zero_counts_kernel() {
    if (threadIdx.x < NEXP) g_counts[threadIdx.x] = 0;
}

// ---------------- kernel 1: router (proven R1) --------------------------------
__global__ void router_kernel(const float* __restrict__ x,
                              const float* __restrict__ gw,
                              const float* __restrict__ gb) {
    int gwarp = (blockIdx.x * blockDim.x + threadIdx.x) >> 5;
    int lane  = threadIdx.x & 31;
    if (gwarp >= NTOK) return;

    const float* xr = x + (size_t)gwarp * DIN;
    float acc[NEXP];
#pragma unroll
    for (int e = 0; e < NEXP; e++) acc[e] = 0.f;

#pragma unroll
    for (int s = 0; s < DIN / 32; s++) {
        int d = s * 32 + lane;
        float xv = __ldg(xr + d);
        const float4* g4 = reinterpret_cast<const float4*>(gw + (size_t)d * NEXP);
        float4 a = __ldg(g4 + 0);
        float4 b = __ldg(g4 + 1);
        float4 c = __ldg(g4 + 2);
        float4 dd = __ldg(g4 + 3);
        acc[0]  += xv * a.x;  acc[1]  += xv * a.y;  acc[2]  += xv * a.z;  acc[3]  += xv * a.w;
        acc[4]  += xv * b.x;  acc[5]  += xv * b.y;  acc[6]  += xv * b.z;  acc[7]  += xv * b.w;
        acc[8]  += xv * c.x;  acc[9]  += xv * c.y;  acc[10] += xv * c.z;  acc[11] += xv * c.w;
        acc[12] += xv * dd.x; acc[13] += xv * dd.y; acc[14] += xv * dd.z; acc[15] += xv * dd.w;
    }
#pragma unroll
    for (int e = 0; e < NEXP; e++) {
#pragma unroll
        for (int off = 16; off > 0; off >>= 1)
            acc[e] += __shfl_xor_sync(0xffffffffu, acc[e], off);
    }
    if (lane == 0) {
        float v[NEXP];
#pragma unroll
        for (int e = 0; e < NEXP; e++) v[e] = acc[e] + gb[e];
        float v0 = v[0]; int e0 = 0;
#pragma unroll
        for (int e = 1; e < NEXP; e++) { if (v[e] > v0) { v0 = v[e]; e0 = e; } }
        float v1 = -3.402823466e38f; int e1 = -1;
#pragma unroll
        for (int e = 0; e < NEXP; e++) { if (e != e0 && v[e] > v1) { v1 = v[e]; e1 = e; } }
        float ex  = expf(v1 - v0);
        float inv = 1.f / (1.f + ex);
        int p0 = atomicAdd(&g_counts[e0], 1);
        g_tok [e0 * NTOK + p0] = gwarp;
        g_dest[e0 * NTOK + p0] = 2 * gwarp;
        g_wt  [e0 * NTOK + p0] = inv;
        int p1 = atomicAdd(&g_counts[e1], 1);
        g_tok [e1 * NTOK + p1] = gwarp;
        g_dest[e1 * NTOK + p1] = 2 * gwarp + 1;
        g_wt  [e1 * NTOK + p1] = ex * inv;
    }
}

// ---------------- kernel 2a: x -> fp16 ----------------------------------------
__global__ void convert_x_kernel(const float* __restrict__ x) {
    int idx = blockIdx.x * blockDim.x + threadIdx.x;        // one float4
    float4 v = reinterpret_cast<const float4*>(x)[idx];
    __half2* ph = reinterpret_cast<__half2*>(g_xh);
    ph[idx * 2 + 0] = __floats2half2_rn(v.x, v.y);
    ph[idx * 2 + 1] = __floats2half2_rn(v.z, v.w);
}

// ---------------- kernel 2b: W -> W^T fp16 (K-major) --------------------------
__global__ void convert_w_kernel(const float* __restrict__ ew) {
    __shared__ float tile[32][33];
    int e  = blockIdx.z;
    int d0 = blockIdx.y * 32;     // din tile
    int o0 = blockIdx.x * 32;     // dout tile
    int tx = threadIdx.x & 31, ty = threadIdx.x >> 5;       // 32x8 threads
    const float* src = ew + ((size_t)e * DIN + d0) * DOUT + o0;
#pragma unroll
    for (int i = 0; i < 4; i++)
        tile[ty + i * 8][tx] = src[(size_t)(ty + i * 8) * DOUT + tx];
    __syncthreads();
#pragma unroll
    for (int i = 0; i < 4; i++) {
        int r = ty + i * 8;                       // output row (n) within tile
        float v = tile[tx][r];                    // = W[d0+tx][o0+r]
        g_wth[((size_t)e * DOUT + o0 + r) * DIN + d0 + tx] = __float2half_rn(v);
    }
}

// ---------------- kernel 3: grouped GEMM, fp16 mma.sync + cp.async + ldmatrix --
__global__ __launch_bounds__(256, 2)
void moe_gemm_kernel(const float* __restrict__ eb) {
    __shared__ __align__(16) uint8_t As[2][ASTAGE];
    __shared__ __align__(16) uint8_t Bs[2][BSTAGE];
    __shared__ int stok[BM];
    __shared__ int s_e, s_mbase, s_cnt;

    const int tid  = threadIdx.x;
    const int lane = tid & 31;
    const int wid  = tid >> 5;
    const int wm   = (wid & 1) * 64;
    const int wn   = (wid >> 1) * 32;

    if (tid == 0) {
        int b = blockIdx.x, acc = 0, e = -1, mb = 0, cn = 0;
        for (int i = 0; i < NEXP; i++) {
            int c = g_counts[i], t = (c + BM - 1) >> 7;
            if (b < acc + t) { e = i; mb = (b - acc) * BM; cn = c; break; }
            acc += t;
        }
        s_e = e; s_mbase = mb; s_cnt = cn;
    }
    __syncthreads();
    const int e = s_e;
    if (e < 0) return;
    const int mbase = s_mbase, cnt = s_cnt;
    const int nbase = blockIdx.y * BN;

    if (tid < BM) {
        int r = mbase + tid;
        stok[tid] = (r < cnt) ? g_tok[e * NTOK + r] : 0;
    }
    __syncthreads();

    const uint32_t Ab = smem_u32(As);
    const uint32_t Bb = smem_u32(Bs);
    const __half* wtp = g_wth + (size_t)(e * DOUT + nbase) * DIN;

    // cp.async mapping: 512 16B-chunks per tile; thread covers {tid, tid+256}
    auto prefetch = [&](int kt, int buf) {
        int k0 = kt * BK;
#pragma unroll
        for (int t = 0; t < 2; t++) {
            int i = tid + t * 256;
            int r = i >> 2, c = i & 3;
            uint32_t dst = Ab + buf * ASTAGE + r * 64 + ((c ^ ((r >> 1) & 3)) << 4);
            cp16(dst, g_xh + (size_t)stok[r] * DIN + k0 + c * 8);
        }
#pragma unroll
        for (int t = 0; t < 2; t++) {
            int i = tid + t * 256;
            int n = i >> 2, c = i & 3;
            uint32_t dst = Bb + buf * BSTAGE + n * 64 + ((c ^ ((n >> 1) & 3)) << 4);
            cp16(dst, wtp + (size_t)n * DIN + k0 + c * 8);
        }
        asm volatile("cp.async.commit_group;" ::: "memory");
    };

    float acc[4][4][4];
#pragma unroll
    for (int i = 0; i < 4; i++)
#pragma unroll
        for (int j = 0; j < 4; j++)
#pragma unroll
            for (int r = 0; r < 4; r++) acc[i][j][r] = 0.f;

    // lane decomposition for ldmatrix addressing
    const int lrow = (lane & 7) | (((lane >> 3) & 1) << 3);  // row within 16 (A)
    const int akc  = (lane >> 4) & 1;                        // A k-chunk parity
    const int bg   = lane >> 3;                              // B group 0..3
    const int brow = (lane & 7) | ((bg & 2) << 2);           // row within 16 (B)
    const int bkc  = bg & 1;                                 // B k-chunk parity

    prefetch(0, 0);

#pragma unroll 1
    for (int s = 0; s < KSTAGES; s++) {
        int buf = s & 1;
        if (s + 1 < KSTAGES) prefetch(s + 1, buf ^ 1);
        if (s + 1 < KSTAGES) asm volatile("cp.async.wait_group 1;" ::: "memory");
        else                 asm volatile("cp.async.wait_group 0;" ::: "memory");
        __syncthreads();

        uint32_t abase = Ab + buf * ASTAGE;
        uint32_t bbase = Bb + buf * BSTAGE;
#pragma unroll
        for (int kk = 0; kk < 2; kk++) {
            uint32_t a[4][4];
#pragma unroll
            for (int mf = 0; mf < 4; mf++) {
                int r = wm + mf * 16 + lrow;
                int c = kk * 2 + akc;
                ldsm_x4(a[mf], abase + r * 64 + ((c ^ ((r >> 1) & 3)) << 4));
            }
            uint32_t b[2][4];   // b[p] = frags for nf=2p (regs 0,1) and nf=2p+1 (regs 2,3)
#pragma unroll
            for (int p = 0; p < 2; p++) {
                int n = wn + p * 16 + brow;
                int c = kk * 2 + bkc;
                // NON-trans: smem rows are n, 16B chunks are k-pairs -> exact B fragment
                ldsm_x4(b[p], bbase + n * 64 + ((c ^ ((n >> 1) & 3)) << 4));
            }
#pragma unroll
            for (int mf = 0; mf < 4; mf++)
#pragma unroll
                for (int nf = 0; nf < 4; nf++)
                    mma16816(acc[mf][nf], a[mf], &b[nf >> 1][(nf & 1) * 2]);
        }
        __syncthreads();
    }

    // ---- epilogue: scale by routing weight, add bias, scatter to unique slot --
    const float* ebp = eb + e * DOUT + nbase;
#pragma unroll
    for (int mf = 0; mf < 4; mf++) {
        int rl0 = wm + mf * 16 + (lane >> 2);
#pragma unroll
        for (int h = 0; h < 2; h++) {
            int r = mbase + rl0 + h * 8;
            if (r < cnt) {
                int dst  = g_dest[e * NTOK + r];
                float w  = g_wt [e * NTOK + r];
                float* outp = g_scratch + (size_t)dst * DOUT + nbase;
#pragma unroll
                for (int nf = 0; nf < 4; nf++) {
                    int n = wn + nf * 8 + (lane & 3) * 2;
                    float b0 = ebp[n], b1 = ebp[n + 1];
                    float2 v;
                    v.x = w * (acc[mf][nf][h * 2 + 0] + b0);
                    v.y = w * (acc[mf][nf][h * 2 + 1] + b1);
                    *reinterpret_cast<float2*>(outp + n) = v;
                }
            }
        }
    }
}

// ---------------- kernel 4: combine -------------------------------------------
__global__ void combine_kernel(float* __restrict__ out) {
    int idx = blockIdx.x * blockDim.x + threadIdx.x;   // float4 index
    int t = idx >> 7;
    int c = idx & 127;
    const float4* s = reinterpret_cast<const float4*>(g_scratch);
    float4 a = s[(size_t)t * 256 + c];
    float4 b = s[(size_t)t * 256 + 128 + c];
    float4 r;
    r.x = a.x + b.x; r.y = a.y + b.y; r.z = a.z + b.z; r.w = a.w + b.w;
    reinterpret_cast<float4*>(out)[idx] = r;
}

// ---------------- launch ------------------------------------------------------
extern "C" void kernel_launch(void* const* d_in, const int* in_sizes, int n_in,
                              void* d_out, int out_size) {
    (void)in_sizes; (void)n_in; (void)out_size;
    const float* x  = (const float*)d_in[0];
    const float* gw = (const float*)d_in[1];
    const float* gb = (const float*)d_in[2];
    const float* ew = (const float*)d_in[3];
    const float* eb = (const float*)d_in[4];
    float* out = (float*)d_out;

    zero_counts_kernel<<<1, 32>>>();
    router_kernel<<<NTOK / 8, 256>>>(x, gw, gb);
    convert_x_kernel<<<(NTOK * DIN / 4) / 256, 256>>>(x);
    convert_w_kernel<<<dim3(DOUT / 32, DIN / 32, NEXP), 256>>>(ew);
    moe_gemm_kernel<<<dim3(MAXTILES, DOUT / BN), 256>>>(eb);
    combine_kernel<<<(NTOK * DOUT / 4) / 256, 256>>>(out);
}